// round 5
// baseline (speedup 1.0000x reference)
#include <cuda_runtime.h>
#include <cuda_bf16.h>
#include <cstddef>

#define DD     768
#define NINS   64
#define HH     64
#define LDX    772        // 768 + 4 pad floats
#define CHUNKK 32
#define NCHUNK (DD / CHUNKK)   // 24

// smem floats: Xs + ownbuf + cvec/w2s/attv/wts + red + Wbuf(2x32x64)
#define SMEM_FLOATS (NINS*LDX + DD + 4*HH + 512 + 2*CHUNKK*HH)
#define SMEM_BYTES  (SMEM_FLOATS * 4)

typedef unsigned long long ull;

__device__ __forceinline__ ull pack2(float lo, float hi) {
    ull r;
    asm("mov.b64 %0, {%1,%2};" : "=l"(r) : "f"(lo), "f"(hi));
    return r;
}
__device__ __forceinline__ void unpack2(ull v, float& lo, float& hi) {
    asm("mov.b64 {%0,%1}, %2;" : "=f"(lo), "=f"(hi) : "l"(v));
}
__device__ __forceinline__ ull fma2(ull a, ull b, ull c) {
    ull d;
    asm("fma.rn.f32x2 %0, %1, %2, %3;" : "=l"(d) : "l"(a), "l"(b), "l"(c));
    return d;
}

__global__ __launch_bounds__(512, 1)
void fused_attn_kernel(const float* __restrict__ inputs,
                       const float* __restrict__ claims,
                       const float* __restrict__ W1,
                       const float* __restrict__ b1,
                       const float* __restrict__ W2,
                       const float* __restrict__ b2,
                       const int*   __restrict__ indexp,
                       float*       __restrict__ out)
{
    extern __shared__ float sm[];
    float* Xs     = sm;                      // [NINS][LDX]
    float* ownbuf = Xs + NINS * LDX;         // [DD]  (also pooling exchange)
    float* cvec   = ownbuf + DD;             // [HH]
    float* w2s    = cvec + HH;               // [HH]
    float* attv   = w2s + HH;                // [HH]
    float* wts    = attv + HH;               // [HH]
    float* red    = wts + HH;                // [512]
    float* Wbuf   = red + 512;               // [2][CHUNKK][HH]

    const int b   = blockIdx.x;
    const int tid = threadIdx.x;

    const float* Xg = inputs + (size_t)b * NINS * DD;

    // ---- Phase 1: load X tile into smem ----
    {
        const float4* src = (const float4*)Xg;
        const int total = NINS * DD / 4;  // 12288; 24 per thread
        #pragma unroll 6
        for (int i = tid; i < total; i += 512) {
            int n  = i / (DD / 4);
            int k4 = i - n * (DD / 4);
            float4 v = __ldg(src + i);
            *(float4*)(Xs + n * LDX + 4 * k4) = v;
        }
    }

    const int index = __ldg(indexp);
    if (index <= -1) {
        const float4* csrc = (const float4*)(claims + (size_t)b * DD);
        for (int i = tid; i < DD / 4; i += 512) {
            float4 v = __ldg(csrc + i);
            *(float4*)(ownbuf + 4 * i) = v;
        }
    }
    if (tid < HH) w2s[tid] = __ldg(W2 + tid);
    __syncthreads();

    const float* ownrow = (index > -1) ? (Xs + index * LDX) : ownbuf;

    // ---- Phase 2: cvec[j] = own . W1a[:,j] + b1[j]  (512 threads, k split 8) ----
    {
        const int prt  = tid >> 6;           // 0..7
        const int j    = tid & 63;
        const int kbeg = prt * (DD / 8);     // 96 k each
        const float* wa = W1 + j;
        float a0 = 0.f, a1 = 0.f, a2 = 0.f, a3 = 0.f;
        #pragma unroll 4
        for (int k = kbeg; k < kbeg + DD / 8; k += 4) {
            a0 = fmaf(ownrow[k + 0], __ldg(wa + (size_t)(k + 0) * HH), a0);
            a1 = fmaf(ownrow[k + 1], __ldg(wa + (size_t)(k + 1) * HH), a1);
            a2 = fmaf(ownrow[k + 2], __ldg(wa + (size_t)(k + 2) * HH), a2);
            a3 = fmaf(ownrow[k + 3], __ldg(wa + (size_t)(k + 3) * HH), a3);
        }
        red[tid] = (a0 + a1) + (a2 + a3);
    }
    __syncthreads();
    if (tid < HH) {
        float s = 0.f;
        #pragma unroll
        for (int p = 0; p < 8; p++) s += red[tid + 64 * p];
        cvec[tid] = s + __ldg(b1 + tid);
    }
    __syncthreads();

    // ---- Phase 3: GEMM  acc[n][j] = sum_k X[n][k] * W1b[k][j] ----
    // Warp = 4 jgl x 8 ngl lanes. Thread: 1 n-row x 8 j-cols, full K=768.
    const int lane = tid & 31;
    const int w    = tid >> 5;
    const int jgl  = lane & 3;
    const int ngl  = lane >> 2;
    const int jh   = w & 1;
    const int nh   = w >> 1;                 // 0..7
    const int j0   = (jh * 4 + jgl) * 8;     // 8 consecutive j
    const int n    = nh * 8 + ngl;

    const float* xrow = Xs + (size_t)n * LDX;

    // staging map: thread stages one float4 per chunk
    const int skk  = tid >> 4;               // 0..31 (k row within chunk)
    const int sc4  = (tid & 15) * 4;         // float col within row
    const float* Wsrc = W1 + (size_t)DD * HH + (size_t)skk * HH + sc4;
    float* Wdst0 = Wbuf + skk * HH + sc4;
    float* Wdst1 = Wbuf + CHUNKK * HH + skk * HH + sc4;

    ull acc[4];
    acc[0] = acc[1] = acc[2] = acc[3] = 0ull;

    // preload chunk 0
    {
        float4 stg = __ldg((const float4*)Wsrc);
        *(float4*)Wdst0 = stg;
    }
    __syncthreads();

    #pragma unroll 1
    for (int c = 0; c < NCHUNK; c++) {
        float4 stg;
        if (c + 1 < NCHUNK)
            stg = __ldg((const float4*)(Wsrc + (size_t)(c + 1) * CHUNKK * HH));

        const float* Wc = Wbuf + (c & 1) * (CHUNKK * HH);
        const float* xc = xrow + c * CHUNKK;

        #pragma unroll
        for (int kk = 0; kk < CHUNKK; kk += 8) {
            float4 xa = *(const float4*)(xc + kk);
            float4 xb = *(const float4*)(xc + kk + 4);
            float xs[8] = {xa.x, xa.y, xa.z, xa.w, xb.x, xb.y, xb.z, xb.w};
            #pragma unroll
            for (int u = 0; u < 8; u++) {
                const float* wr = Wc + (kk + u) * HH + j0;
                ulonglong2 w01 = *(const ulonglong2*)(wr);
                ulonglong2 w23 = *(const ulonglong2*)(wr + 4);
                ull xx = pack2(xs[u], xs[u]);
                acc[0] = fma2(xx, w01.x, acc[0]);
                acc[1] = fma2(xx, w01.y, acc[1]);
                acc[2] = fma2(xx, w23.x, acc[2]);
                acc[3] = fma2(xx, w23.y, acc[3]);
            }
        }

        if (c + 1 < NCHUNK)
            *(float4*)(((c & 1) == 0) ? Wdst1 : Wdst0) = stg;
        __syncthreads();
    }

    // ---- Phase 4: epilogue  att[n] = sum_j relu(acc + cvec[j]) * W2[j] ----
    {
        float ap = 0.f;
        #pragma unroll
        for (int q = 0; q < 4; q++) {
            float h0, h1;
            unpack2(acc[q], h0, h1);
            int jj = j0 + 2 * q;
            h0 = fmaxf(h0 + cvec[jj], 0.f);
            h1 = fmaxf(h1 + cvec[jj + 1], 0.f);
            ap = fmaf(h0, w2s[jj], ap);
            ap = fmaf(h1, w2s[jj + 1], ap);
        }
        // reduce over jgl lanes (bits 0-1)
        ap += __shfl_xor_sync(0xffffffffu, ap, 1);
        ap += __shfl_xor_sync(0xffffffffu, ap, 2);
        if (jgl == 0) red[n * 2 + jh] = ap;
    }
    __syncthreads();
    if (tid < HH) attv[tid] = red[2 * tid] + red[2 * tid + 1];
    __syncthreads();

    // ---- Phase 5: softmax over 64 instances (single warp) ----
    if (tid < 32) {
        float a0 = attv[tid], a1 = attv[tid + 32];
        float m = fmaxf(a0, a1);
        #pragma unroll
        for (int off = 16; off > 0; off >>= 1)
            m = fmaxf(m, __shfl_xor_sync(0xffffffffu, m, off));
        float e0 = expf(a0 - m), e1 = expf(a1 - m);
        float s = e0 + e1;
        #pragma unroll
        for (int off = 16; off > 0; off >>= 1)
            s += __shfl_xor_sync(0xffffffffu, s, off);
        float inv = 1.0f / s;
        wts[tid]      = e0 * inv;
        wts[tid + 32] = e1 * inv;
    }
    __syncthreads();

    // ---- Phase 6: pooling  out[b][d] = sum_n wts[n] * X[n][d] ----
    // 384 active threads: 192 float4 columns x 2 n-halves; exchange via ownbuf.
    const int half = tid / 192;              // 0,1 active; 2 idle-ish
    const int col  = tid % 192;
    float4 a = make_float4(0.f, 0.f, 0.f, 0.f);
    if (tid < 384) {
        const float* xcol = Xs + 4 * col + (size_t)half * 32 * LDX;
        const float* wp = wts + half * 32;
        #pragma unroll 8
        for (int nn = 0; nn < 32; nn++) {
            float wn = wp[nn];
            float4 xv = *(const float4*)(xcol + (size_t)nn * LDX);
            a.x = fmaf(wn, xv.x, a.x);
            a.y = fmaf(wn, xv.y, a.y);
            a.z = fmaf(wn, xv.z, a.z);
            a.w = fmaf(wn, xv.w, a.w);
        }
        if (half == 1) *(float4*)(ownbuf + 4 * col) = a;
    }
    __syncthreads();
    if (tid < 192) {
        float4 bq = *(const float4*)(ownbuf + 4 * col);
        a.x += bq.x; a.y += bq.y; a.z += bq.z; a.w += bq.w;
        *(float4*)(out + (size_t)b * DD + 4 * col) = a;
    }
}

extern "C" void kernel_launch(void* const* d_in, const int* in_sizes, int n_in,
                              void* d_out, int out_size)
{
    const float* inputs = (const float*)d_in[0];
    const float* claims = (const float*)d_in[1];
    const float* W1     = (const float*)d_in[2];
    const float* b1     = (const float*)d_in[3];
    const float* W2     = (const float*)d_in[4];
    const float* b2     = (const float*)d_in[5];
    const int*   indexp = (const int*)d_in[6];
    float*       out    = (float*)d_out;

    const int B = in_sizes[0] / (NINS * DD);

    cudaFuncSetAttribute(fused_attn_kernel,
                         cudaFuncAttributeMaxDynamicSharedMemorySize, SMEM_BYTES);
    fused_attn_kernel<<<B, 512, SMEM_BYTES>>>(inputs, claims, W1, b1, W2, b2,
                                              indexp, out);
}